// round 8
// baseline (speedup 1.0000x reference)
#include <cuda_runtime.h>
#include <cuda_bf16.h>

// Fixed by the reference: 2048x2048 fp32, pass1 box = 17(v) x 5(h),
// pass2 box = 5(v) x 17(h); out = Xin + boxsum(y - Xin)/Ncount, zero-padded.
#define H_DIM 2048
#define W_DIM 2048

// 16 MB static scratch for the intermediate X1 (no allocations allowed).
__device__ float g_X1[H_DIM * W_DIM];

__device__ __forceinline__ float4 ld4(const float* p) { return *(const float4*)p; }
__device__ __forceinline__ float4 sub4(float4 a, float4 b) {
    return make_float4(a.x - b.x, a.y - b.y, a.z - b.z, a.w - b.w);
}
__device__ __forceinline__ void acc4(float4& a, float4 b) {
    a.x += b.x; a.y += b.y; a.z += b.z; a.w += b.w;
}
__device__ __forceinline__ void accsub4(float4& a, float4 n, float4 o) {
    a.x += n.x - o.x; a.y += n.y - o.y; a.z += n.z - o.z; a.w += n.w - o.w;
}

template <int RV, int RH>
__global__ __launch_bounds__(256)
void guided_pass(const float* __restrict__ Xin,
                 const float* __restrict__ Y,
                 float* __restrict__ out)
{
    constexpr int TILE_H = 64, TILE_W = 64;
    constexpr int CL  = (RH + 3) & ~3;      // float4-aligned horiz halo (4 / 8)
    constexpr int WH  = TILE_W + 2 * CL;    // staged width: 72 / 80
    constexpr int WHP = WH + 4;             // padded row stride: 76 / 84
    constexpr int W4  = WH / 4;             // float4 cols: 18 / 20
    constexpr int NT_A = W4 * 8;            // phase-A threads: 144 / 160
    constexpr int NTAPV = 2 * RV + 1;
    constexpr int NTAPH = 2 * RH + 1;
    constexpr float INV_N = 1.0f / (float)(NTAPV * NTAPH);
    constexpr int O  = CL - RH;             // sVS col offset of output col 0's window
    constexpr int LW = 8 + 2 * CL;          // register window length (16 / 24)

    __shared__ __align__(16) float sVS[TILE_H][WHP];  // vertical (2RV+1)-sums of D

    const int bx  = blockIdx.x * TILE_W;
    const int by  = blockIdx.y * TILE_H;
    const int tid = threadIdx.x;

    const bool interior = (by >= RV) && (by + TILE_H + RV <= H_DIM)
                       && (bx >= CL) && (bx + TILE_W + CL <= W_DIM);

    // ================= Phase A: vertical sums in registers ==================
    if (tid < NT_A) {
        const int c4 = tid % W4;
        const int r0 = (tid / W4) * 8;       // 8-row output segment
        const int gj0 = bx - CL + 4 * c4;

        if (interior) {
            const int base = (by + r0) * W_DIM + gj0;   // row by+r0, this col group
            const float* yp = Y   + base;
            const float* xp = Xin + base;

            if constexpr (RV <= 2) {
                // Ring-buffer sliding window (small RV).
                float4 ring[NTAPV];
                float4 vs = make_float4(0.f, 0.f, 0.f, 0.f);
                #pragma unroll
                for (int k = 0; k < NTAPV; k++) {
                    const int off = (k - RV) * W_DIM;
                    ring[k] = sub4(ld4(yp + off), ld4(xp + off));
                    acc4(vs, ring[k]);
                }
                *(float4*)&sVS[r0][4 * c4] = vs;
                #pragma unroll
                for (int rr = 1; rr < 8; rr++) {
                    const int off = (rr + RV) * W_DIM;
                    const float4 nv = sub4(ld4(yp + off), ld4(xp + off));
                    accsub4(vs, nv, ring[(rr - 1) % NTAPV]);
                    ring[(rr - 1) % NTAPV] = nv;
                    *(float4*)&sVS[r0 + rr][4 * c4] = vs;
                }
            } else {
                // Reload-sliding (large RV): old rows re-fetched, L1 hits.
                float4 vs = make_float4(0.f, 0.f, 0.f, 0.f);
                #pragma unroll
                for (int k = 0; k < NTAPV; k++) {
                    const int off = (k - RV) * W_DIM;
                    acc4(vs, sub4(ld4(yp + off), ld4(xp + off)));
                }
                *(float4*)&sVS[r0][4 * c4] = vs;
                #pragma unroll
                for (int rr = 1; rr < 8; rr++) {
                    const int offN = (rr + RV) * W_DIM;
                    const int offO = (rr - 1 - RV) * W_DIM;
                    const float4 nv = sub4(ld4(yp + offN), ld4(xp + offN));
                    const float4 ov = sub4(ld4(yp + offO), ld4(xp + offO));
                    accsub4(vs, nv, ov);
                    *(float4*)&sVS[r0 + rr][4 * c4] = vs;
                }
            }
        } else {
            // Boundary: scalar predicated loads, zero outside image.
            auto loadD = [&](int gi, int gj) -> float {
                if (gi < 0 || gi >= H_DIM || gj < 0 || gj >= W_DIM) return 0.f;
                const int g = gi * W_DIM + gj;
                return Y[g] - Xin[g];
            };
            float vs[4] = {0.f, 0.f, 0.f, 0.f};
            #pragma unroll
            for (int k = 0; k < NTAPV; k++) {
                const int gi = by + r0 - RV + k;
                #pragma unroll
                for (int m = 0; m < 4; m++) vs[m] += loadD(gi, gj0 + m);
            }
            #pragma unroll
            for (int m = 0; m < 4; m++) sVS[r0][4 * c4 + m] = vs[m];
            #pragma unroll
            for (int rr = 1; rr < 8; rr++) {
                const int giN = by + r0 + RV + rr;
                const int giO = by + r0 - RV + rr - 1;
                #pragma unroll
                for (int m = 0; m < 4; m++)
                    vs[m] += loadD(giN, gj0 + m) - loadD(giO, gj0 + m);
                #pragma unroll
                for (int m = 0; m < 4; m++) sVS[r0 + rr][4 * c4 + m] = vs[m];
            }
        }
    }
    __syncthreads();

    // ======== Phase B: horizontal sliding window in registers + epilogue ====
    const int c0 = (tid & 7) * 8;            // first of 8 output cols
    #pragma unroll
    for (int rp = 0; rp < 2; rp++) {
        const int row = (tid >> 3) + 32 * rp;
        float v[LW];
        #pragma unroll
        for (int q = 0; q < LW / 4; q++) {
            const float4 t = *(const float4*)&sVS[row][c0 + 4 * q];
            v[4*q] = t.x; v[4*q+1] = t.y; v[4*q+2] = t.z; v[4*q+3] = t.w;
        }
        float hs = 0.f;
        #pragma unroll
        for (int k = 0; k < NTAPH; k++) hs += v[O + k];

        const float* xrow = Xin + (by + row) * W_DIM + bx + c0;
        const float4 x0 = ld4(xrow);
        const float4 x1 = ld4(xrow + 4);
        const float xs[8] = {x0.x, x0.y, x0.z, x0.w, x1.x, x1.y, x1.z, x1.w};
        float o[8];
        if (interior) {
            #pragma unroll
            for (int i = 0; i < 8; i++) {
                o[i] = xs[i] + hs * INV_N;
                if (i < 7) hs += v[O + NTAPH + i] - v[O + i];
            }
        } else {
            const int gi = by + row;
            const int nh = min(gi + RV, H_DIM - 1) - max(gi - RV, 0) + 1;
            #pragma unroll
            for (int i = 0; i < 8; i++) {
                const int gj = bx + c0 + i;
                const int nw = min(gj + RH, W_DIM - 1) - max(gj - RH, 0) + 1;
                o[i] = xs[i] + hs * __frcp_rn((float)(nh * nw));
                if (i < 7) hs += v[O + NTAPH + i] - v[O + i];
            }
        }
        float* orow = out + (by + row) * W_DIM + bx + c0;
        *(float4*)(orow)     = make_float4(o[0], o[1], o[2], o[3]);
        *(float4*)(orow + 4) = make_float4(o[4], o[5], o[6], o[7]);
    }
}

extern "C" void kernel_launch(void* const* d_in, const int* in_sizes, int n_in,
                              void* d_out, int out_size)
{
    const float* X = (const float*)d_in[0];
    const float* Y = (const float*)d_in[1];
    // d_in[2] is the (2,1,17,17) kernel tensor; fixed 17x5 / 5x17 boxes hard-coded.
    float* out = (float*)d_out;

    float* X1;
    cudaGetSymbolAddress((void**)&X1, g_X1);

    dim3 block(256);
    dim3 grid(W_DIM / 64, H_DIM / 64);

    // Pass 1: vertical radius 8, horizontal radius 2  ->  X1 (scratch)
    guided_pass<8, 2><<<grid, block>>>(X, Y, X1);
    // Pass 2: vertical radius 2, horizontal radius 8  ->  final output
    guided_pass<2, 8><<<grid, block>>>(X1, Y, out);
}

// round 9
// speedup vs baseline: 1.5905x; 1.5905x over previous
#include <cuda_runtime.h>
#include <cuda_bf16.h>

// Fixed by the reference: 2048x2048 fp32, pass1 box = 17(v) x 5(h),
// pass2 box = 5(v) x 17(h); out = Xin + boxsum(y - Xin)/Ncount, zero-padded.
#define H_DIM 2048
#define W_DIM 2048

// 16 MB static scratch for the intermediate X1 (no allocations allowed).
__device__ float g_X1[H_DIM * W_DIM];

__device__ __forceinline__ float4 z4() { return make_float4(0.f, 0.f, 0.f, 0.f); }
__device__ __forceinline__ float4 add4(float4 a, float4 b) {
    return make_float4(a.x + b.x, a.y + b.y, a.z + b.z, a.w + b.w);
}
__device__ __forceinline__ float4 sub4(float4 a, float4 b) {
    return make_float4(a.x - b.x, a.y - b.y, a.z - b.z, a.w - b.w);
}

// Horizontal (2*RH+1)-tap box sum across the warp's 128 columns.
// tot holds the vertical sums for this thread's 4 columns (c = 4*lane + i,
// strip-local). Valid for output lanes only (halo lanes absorb edge effects).
template <int RH>
__device__ __forceinline__ float4 hsum_warp(float4 t) {
    const unsigned M = 0xffffffffu;
    if constexpr (RH == 2) {
        // window c-2..c+2  (output lanes 1..30)
        const float Lz = __shfl_up_sync(M, t.z, 1);
        const float Lw = __shfl_up_sync(M, t.w, 1);
        const float Rx = __shfl_down_sync(M, t.x, 1);
        const float Ry = __shfl_down_sync(M, t.y, 1);
        const float sall = t.x + t.y + t.z + t.w;
        float4 hs;
        hs.y = Lw + sall;              // c-2..c+2 for i=1
        hs.x = hs.y + Lz - t.w;        // i=0
        hs.z = sall + Rx;              // i=2
        hs.w = hs.z - t.x + Ry;        // i=3
        return hs;
    } else {
        // RH == 8: window c-8..c+8  (output lanes 2..29)
        const float S    = t.x + t.y + t.z + t.w;
        const float Sm2  = __shfl_up_sync(M, S, 2);
        const float Sm1  = __shfl_up_sync(M, S, 1);
        const float Sp1  = __shfl_down_sync(M, S, 1);
        const float dxm2 = __shfl_up_sync(M, t.x, 2);
        const float dym2 = __shfl_up_sync(M, t.y, 2);
        const float dzm2 = __shfl_up_sync(M, t.z, 2);
        const float dxp2 = __shfl_down_sync(M, t.x, 2);
        const float dyp2 = __shfl_down_sync(M, t.y, 2);
        const float dzp2 = __shfl_down_sync(M, t.z, 2);
        const float dwp2 = __shfl_down_sync(M, t.w, 2);
        float4 hs;
        hs.x = Sm2 + Sm1 + S + Sp1 + dxp2;  // cols 4t-8 .. 4t+8
        hs.y = hs.x - dxm2 + dyp2;
        hs.z = hs.y - dym2 + dzp2;
        hs.w = hs.z - dzm2 + dwp2;
        return hs;
    }
}

template <int RV, int RH>
__global__ __launch_bounds__(256)
void guided_pass(const float* __restrict__ Xin,
                 const float* __restrict__ Y,
                 float* __restrict__ out)
{
    constexpr int OUTW   = (RH == 8) ? 112 : 120;  // output cols per warp strip
    constexpr int LANELO = (RH == 8) ? 2 : 1;      // first output lane
    constexpr int LANEHI = (RH == 8) ? 29 : 30;    // last output lane
    constexpr int STRIPS = (W_DIM + OUTW - 1) / OUTW;   // 19 / 18
    constexpr int SEG    = (RV == 8) ? 16 : 8;          // rows per warp segment
    constexpr int SEGS   = H_DIM / SEG;

    const int wg    = blockIdx.x * 8 + (threadIdx.x >> 5);
    const int lane  = threadIdx.x & 31;
    const int strip = wg % STRIPS;
    const int segy  = wg / STRIPS;
    if (segy >= SEGS) return;

    const int r0  = segy * SEG;
    const int gj0 = strip * OUTW - 4 * LANELO + 4 * lane;  // 4-aligned
    const bool colIn = (gj0 >= 0) && (gj0 + 3 < W_DIM);

    // D = Y - Xin at row gi, this thread's 4 columns (zero outside image).
    auto loadD = [&](int gi) -> float4 {
        if ((unsigned)gi >= (unsigned)H_DIM) return z4();
        const float* yp = Y   + (size_t)gi * W_DIM + gj0;
        const float* xp = Xin + (size_t)gi * W_DIM + gj0;
        if (colIn) return sub4(*(const float4*)yp, *(const float4*)xp);
        float4 r = z4();
        if (gj0 + 0 >= 0 && gj0 + 0 < W_DIM) r.x = yp[0] - xp[0];
        if (gj0 + 1 >= 0 && gj0 + 1 < W_DIM) r.y = yp[1] - xp[1];
        if (gj0 + 2 >= 0 && gj0 + 2 < W_DIM) r.z = yp[2] - xp[2];
        if (gj0 + 3 >= 0 && gj0 + 3 < W_DIM) r.w = yp[3] - xp[3];
        return r;
    };

    // Per-column 1/nw (clamped horizontal window count).
    float4 invnw;
    {
        auto f = [&](int gj) {
            int nw = min(gj + RH, W_DIM - 1) - max(gj - RH, 0) + 1;
            return __frcp_rn((float)max(nw, 1));
        };
        invnw = make_float4(f(gj0), f(gj0 + 1), f(gj0 + 2), f(gj0 + 3));
    }
    const bool storeOK = (lane >= LANELO) && (lane <= LANEHI) && (gj0 + 3 < W_DIM);

    // Emit one output row from its vertical-sum float4 (all lanes participate
    // in the shuffles; only storeOK lanes write).
    auto emit = [&](int gi, float4 tot) {
        const float4 hs = hsum_warp<RH>(tot);
        const int nh = min(gi + RV, H_DIM - 1) - max(gi - RV, 0) + 1;
        const float invnh = __frcp_rn((float)nh);
        if (storeOK) {
            const float4 xv = *(const float4*)(Xin + (size_t)gi * W_DIM + gj0);
            float4 o;
            o.x = fmaf(hs.x * invnh, invnw.x, xv.x);
            o.y = fmaf(hs.y * invnh, invnw.y, xv.y);
            o.z = fmaf(hs.z * invnh, invnw.z, xv.z);
            o.w = fmaf(hs.w * invnh, invnw.w, xv.w);
            *(float4*)(out + (size_t)gi * W_DIM + gj0) = o;
        }
    };

    if constexpr (RV == 2) {
        // Ring-buffer vertical sliding window (window 5).
        float4 ring[4];
        float4 vs = z4();
        #pragma unroll
        for (int k = 0; k < 4; k++) {          // rows r0-2 .. r0+1
            ring[k] = loadD(r0 - 2 + k);
            vs = add4(vs, ring[k]);
        }
        #pragma unroll
        for (int rr = 0; rr < SEG; rr++) {
            const int gi = r0 + rr;
            const float4 nv  = loadD(gi + 2);
            const float4 tot = add4(vs, nv);   // rows gi-2 .. gi+2
            emit(gi, tot);
            vs = sub4(tot, ring[rr & 3]);      // drop row gi-2
            ring[rr & 3] = nv;
        }
    } else {
        // Reload-sliding vertical window (window 17); old rows re-fetched
        // (L1/L2 hits — they were read 17 rows ago by this warp).
        float4 vs = z4();
        #pragma unroll
        for (int k = 0; k < 16; k++)           // rows r0-8 .. r0+7
            vs = add4(vs, loadD(r0 - 8 + k));
        #pragma unroll
        for (int rr = 0; rr < SEG; rr++) {
            const int gi = r0 + rr;
            const float4 nv  = loadD(gi + 8);
            const float4 tot = add4(vs, nv);   // rows gi-8 .. gi+8
            emit(gi, tot);
            const float4 ov = loadD(gi - 8);
            vs = sub4(tot, ov);
        }
    }
}

extern "C" void kernel_launch(void* const* d_in, const int* in_sizes, int n_in,
                              void* d_out, int out_size)
{
    const float* X = (const float*)d_in[0];
    const float* Y = (const float*)d_in[1];
    // d_in[2] is the (2,1,17,17) kernel tensor; fixed 17x5 / 5x17 boxes hard-coded.
    float* out = (float*)d_out;

    float* X1;
    cudaGetSymbolAddress((void**)&X1, g_X1);

    // Pass 1: RV=8, RH=2.  strips=18, SEG=16 -> 18*128 warps = 288 blocks.
    guided_pass<8, 2><<<288, 256>>>(X, Y, X1);
    // Pass 2: RV=2, RH=8.  strips=19, SEG=8  -> 19*256 warps = 608 blocks.
    guided_pass<2, 8><<<608, 256>>>(X1, Y, out);
}